// round 14
// baseline (speedup 1.0000x reference)
#include <cuda_runtime.h>
#include <cuda_fp16.h>
#include <mma.h>
#include <cstdint>

using namespace nvcuda;

#define N_NODES 100000
#define IN_F    256
#define OUT_F   128
#define N_EDGES 3200000

// ---- scratch (device globals per allocation rules) ----
__device__ __align__(256) __half g_hh[(size_t)N_NODES * OUT_F];  // xW in fp16, 25.6 MB
__device__ int2 g_edges[N_EDGES];                 // dst-sorted (src, valbits)
__device__ int  g_hist[N_NODES];
__device__ int  g_locExc[N_NODES];
__device__ int  g_blockSums[512];
__device__ int  g_offsets[N_NODES];
__device__ int  g_cursor[N_NODES];

// ---------------------------------------------------------------------------
// Counting sort of edges by dst
// ---------------------------------------------------------------------------
__global__ void zero_hist_kernel() {
    int i = blockIdx.x * blockDim.x + threadIdx.x;
    int stride = gridDim.x * blockDim.x;
    for (; i < N_NODES; i += stride) g_hist[i] = 0;
}

__global__ void hist_kernel(const int* __restrict__ dst, int E) {
    int e = blockIdx.x * blockDim.x + threadIdx.x;
    if (e < E) atomicAdd(&g_hist[dst[e]], 1);
}

__global__ void scan1_kernel(int n) {
    __shared__ int sm[256];
    int i = blockIdx.x * 256 + threadIdx.x;
    int v = (i < n) ? g_hist[i] : 0;
    sm[threadIdx.x] = v;
    __syncthreads();
#pragma unroll
    for (int off = 1; off < 256; off <<= 1) {
        int add = (threadIdx.x >= off) ? sm[threadIdx.x - off] : 0;
        __syncthreads();
        sm[threadIdx.x] += add;
        __syncthreads();
    }
    if (i < n) g_locExc[i] = sm[threadIdx.x] - v;
    if (threadIdx.x == 255) g_blockSums[blockIdx.x] = sm[255];
}

__global__ void scan2_kernel(int nb) {
    __shared__ int sm[512];
    int t = threadIdx.x;
    int v = (t < nb) ? g_blockSums[t] : 0;
    sm[t] = v;
    __syncthreads();
#pragma unroll
    for (int off = 1; off < 512; off <<= 1) {
        int add = (t >= off) ? sm[t - off] : 0;
        __syncthreads();
        sm[t] += add;
        __syncthreads();
    }
    g_blockSums[t] = sm[t] - v;
}

__global__ void scan3_kernel(int n) {
    int i = blockIdx.x * blockDim.x + threadIdx.x;
    if (i < n) {
        int o = g_locExc[i] + g_blockSums[i >> 8];
        g_offsets[i] = o;
        g_cursor[i]  = o;
    }
}

__global__ void scatter_kernel(const int* __restrict__ src,
                               const int* __restrict__ dst,
                               const float* __restrict__ vals, int E) {
    int e = blockIdx.x * blockDim.x + threadIdx.x;
    if (e < E) {
        int d = dst[e];
        int pos = atomicAdd(&g_cursor[d], 1);
        g_edges[pos] = make_int2(src[e], __float_as_int(vals[e]));
    }
}

// ---------------------------------------------------------------------------
// GEMM: g_hh = fp16(x @ W)  via single-pass TF32 tensor-core MMA.
//   Block 64(M) x 128(N), BK=32. 8 warps (4 M x 2 N), 16x64 per warp.
//   TF32 mantissa (2^-11) matches the fp16 storage precision of g_hh.
// ---------------------------------------------------------------------------
#define BM 64
#define BN 128
#define BK 32

__global__ __launch_bounds__(256)
void gemm_tf32_kernel(const float* __restrict__ X,
                      const float* __restrict__ W, int M) {
    __shared__ __align__(16) float As[BM][36];    // 64x32, pad 4
    __shared__ __align__(16) float Bs[BK][132];   // 32x128, pad 4
    __shared__ float patch[8][16][20];            // epilogue staging

    const int t = threadIdx.x;
    const int blockRow = blockIdx.x * BM;
    const int w = t >> 5;
    const int warpM = w >> 1;            // 0..3
    const int warpN = w & 1;             // 0..1

    wmma::fragment<wmma::accumulator, 16, 16, 8, float> acc[4];
#pragma unroll
    for (int n = 0; n < 4; n++) wmma::fill_fragment(acc[n], 0.0f);

    for (int k0 = 0; k0 < IN_F; k0 += BK) {
        // A tile: 64x32 fp32, 512 float4, 2 per thread
#pragma unroll
        for (int i = 0; i < 2; i++) {
            int idx = t + i * 256;
            int arow = idx >> 3;
            int acol = (idx & 7) * 4;
            int grow = blockRow + arow;
            float4 v = make_float4(0.f, 0.f, 0.f, 0.f);
            if (grow < M)
                v = *reinterpret_cast<const float4*>(X + (size_t)grow * IN_F + k0 + acol);
            As[arow][acol + 0] = v.x;
            As[arow][acol + 1] = v.y;
            As[arow][acol + 2] = v.z;
            As[arow][acol + 3] = v.w;
        }
        // B tile: 32x128 fp32, 1024 float4, 4 per thread
#pragma unroll
        for (int i = 0; i < 4; i++) {
            int idx = t + i * 256;
            int brow = idx >> 5;
            int bcol = (idx & 31) * 4;
            float4 v = *reinterpret_cast<const float4*>(W + (size_t)(k0 + brow) * OUT_F + bcol);
            Bs[brow][bcol + 0] = v.x;
            Bs[brow][bcol + 1] = v.y;
            Bs[brow][bcol + 2] = v.z;
            Bs[brow][bcol + 3] = v.w;
        }
        __syncthreads();

#pragma unroll
        for (int kk = 0; kk < BK; kk += 8) {
            wmma::fragment<wmma::matrix_a, 16, 16, 8, wmma::precision::tf32, wmma::row_major> a;
            wmma::load_matrix_sync(a, &As[warpM * 16][kk], 36);
#pragma unroll
            for (int e = 0; e < a.num_elements; e++)
                a.x[e] = wmma::__float_to_tf32(a.x[e]);
#pragma unroll
            for (int n = 0; n < 4; n++) {
                wmma::fragment<wmma::matrix_b, 16, 16, 8, wmma::precision::tf32, wmma::row_major> b;
                int col = warpN * 64 + n * 16;
                wmma::load_matrix_sync(b, &Bs[kk][col], 132);
#pragma unroll
                for (int e = 0; e < b.num_elements; e++)
                    b.x[e] = wmma::__float_to_tf32(b.x[e]);
                wmma::mma_sync(acc[n], a, b, acc[n]);
            }
        }
        __syncthreads();
    }

    // Epilogue: stage via smem, convert to fp16, store 8 halves (16B) per lane.
    const int lane = t & 31;
    const int rowBase = blockRow + warpM * 16;
#pragma unroll
    for (int n = 0; n < 4; n++) {
        wmma::store_matrix_sync(&patch[w][0][0], acc[n], 20, wmma::mem_row_major);
        __syncwarp();
        int r = lane >> 1;
        int cbase = (lane & 1) * 8;
        int grow = rowBase + r;
        int gcol = warpN * 64 + n * 16 + cbase;
        if (grow < M) {
            __half2 h01 = __floats2half2_rn(patch[w][r][cbase + 0], patch[w][r][cbase + 1]);
            __half2 h23 = __floats2half2_rn(patch[w][r][cbase + 2], patch[w][r][cbase + 3]);
            __half2 h45 = __floats2half2_rn(patch[w][r][cbase + 4], patch[w][r][cbase + 5]);
            __half2 h67 = __floats2half2_rn(patch[w][r][cbase + 6], patch[w][r][cbase + 7]);
            uint4 pk;
            pk.x = *reinterpret_cast<uint32_t*>(&h01);
            pk.y = *reinterpret_cast<uint32_t*>(&h23);
            pk.z = *reinterpret_cast<uint32_t*>(&h45);
            pk.w = *reinterpret_cast<uint32_t*>(&h67);
            *reinterpret_cast<uint4*>(&g_hh[(size_t)grow * OUT_F + gcol]) = pk;
        }
        __syncwarp();
    }
}

// ---------------------------------------------------------------------------
// SpMM: warp per dst node over its sorted segment, 4-edge unrolled gathers
// for MLP. out[i] = sum(val * h[src]) + (sum val) * bias
// ---------------------------------------------------------------------------
__device__ __forceinline__ void fma_h4(float4& acc, float v, uint2 raw) {
    __half2 h01 = *reinterpret_cast<__half2*>(&raw.x);
    __half2 h23 = *reinterpret_cast<__half2*>(&raw.y);
    float2 f01 = __half22float2(h01);
    float2 f23 = __half22float2(h23);
    acc.x = fmaf(v, f01.x, acc.x);
    acc.y = fmaf(v, f01.y, acc.y);
    acc.z = fmaf(v, f23.x, acc.z);
    acc.w = fmaf(v, f23.y, acc.w);
}

__global__ __launch_bounds__(256)
void spmm_kernel(const float* __restrict__ bias, float* __restrict__ out) {
    int node = (blockIdx.x * 256 + threadIdx.x) >> 5;
    int lane = threadIdx.x & 31;
    if (node >= N_NODES) return;

    int start = g_offsets[node];
    int cnt   = g_hist[node];

    float4 acc = make_float4(0.f, 0.f, 0.f, 0.f);
    float sumv = 0.f;
    const size_t colOff = (size_t)lane * 4;

    for (int base = 0; base < cnt; base += 32) {
        int n = cnt - base;
        if (n > 32) n = 32;
        int2 p = make_int2(0, 0);
        if (lane < n) p = g_edges[start + base + lane];

        int j = 0;
        for (; j + 4 <= n; j += 4) {
            int   s0 = __shfl_sync(0xffffffffu, p.x, j + 0);
            int   s1 = __shfl_sync(0xffffffffu, p.x, j + 1);
            int   s2 = __shfl_sync(0xffffffffu, p.x, j + 2);
            int   s3 = __shfl_sync(0xffffffffu, p.x, j + 3);
            float v0 = __int_as_float(__shfl_sync(0xffffffffu, p.y, j + 0));
            float v1 = __int_as_float(__shfl_sync(0xffffffffu, p.y, j + 1));
            float v2 = __int_as_float(__shfl_sync(0xffffffffu, p.y, j + 2));
            float v3 = __int_as_float(__shfl_sync(0xffffffffu, p.y, j + 3));
            // 4 independent gathers in flight (MLP=4)
            uint2 r0 = *reinterpret_cast<const uint2*>(g_hh + (size_t)s0 * OUT_F + colOff);
            uint2 r1 = *reinterpret_cast<const uint2*>(g_hh + (size_t)s1 * OUT_F + colOff);
            uint2 r2 = *reinterpret_cast<const uint2*>(g_hh + (size_t)s2 * OUT_F + colOff);
            uint2 r3 = *reinterpret_cast<const uint2*>(g_hh + (size_t)s3 * OUT_F + colOff);
            fma_h4(acc, v0, r0);
            fma_h4(acc, v1, r1);
            fma_h4(acc, v2, r2);
            fma_h4(acc, v3, r3);
            sumv += (v0 + v1) + (v2 + v3);
        }
        for (; j < n; j++) {
            int   s  = __shfl_sync(0xffffffffu, p.x, j);
            float vi = __int_as_float(__shfl_sync(0xffffffffu, p.y, j));
            uint2 r = *reinterpret_cast<const uint2*>(g_hh + (size_t)s * OUT_F + colOff);
            fma_h4(acc, vi, r);
            sumv += vi;
        }
    }

    float4 b = *reinterpret_cast<const float4*>(bias + colOff);
    float4 o;
    o.x = fmaf(sumv, b.x, acc.x);
    o.y = fmaf(sumv, b.y, acc.y);
    o.z = fmaf(sumv, b.z, acc.z);
    o.w = fmaf(sumv, b.w, acc.w);
    *reinterpret_cast<float4*>(out + (size_t)node * OUT_F + colOff) = o;
}

// ---------------------------------------------------------------------------
// Launch. Inputs: x, edge_src, edge_dst, edge_vals, weight, bias
// ---------------------------------------------------------------------------
extern "C" void kernel_launch(void* const* d_in, const int* in_sizes, int n_in,
                              void* d_out, int out_size) {
    const float* x        = (const float*)d_in[0];
    const int*   edge_src = (const int*)d_in[1];
    const int*   edge_dst = (const int*)d_in[2];
    const float* edge_val = (const float*)d_in[3];
    const float* weight   = (const float*)d_in[4];
    const float* bias     = (const float*)d_in[5];
    float*       out      = (float*)d_out;

    const int M = in_sizes[0] / IN_F;        // 100000
    const int E = in_sizes[1];               // 3200000
    const int nScanBlocks = (N_NODES + 255) / 256;   // 391

    zero_hist_kernel<<<256, 256>>>();
    hist_kernel<<<(E + 255) / 256, 256>>>(edge_dst, E);
    scan1_kernel<<<nScanBlocks, 256>>>(N_NODES);
    scan2_kernel<<<1, 512>>>(nScanBlocks);
    gemm_tf32_kernel<<<(M + BM - 1) / BM, 256>>>(x, weight, M);
    scan3_kernel<<<nScanBlocks, 256>>>(N_NODES);
    scatter_kernel<<<(E + 255) / 256, 256>>>(edge_src, edge_dst, edge_val, E);
    spmm_kernel<<<(N_NODES * 32 + 255) / 256, 256>>>(bias, out);
}